// round 1
// baseline (speedup 1.0000x reference)
#include <cuda_runtime.h>
#include <math.h>

#define BB   64
#define TT   256
#define IDIM 512
#define HDIM 1024
#define G4   4096   // 4*HDIM

// ---- device scratch (allocation-free rule: __device__ globals) ----
__device__ float g_gates[(size_t)TT * BB * G4];  // [T][B][4H]  (256 MB)
__device__ float g_WhR[(size_t)HDIM * G4];       // Wh re-laid: [k][j*4+g] (16 MB)
__device__ float g_h[2][BB * HDIM];              // double-buffered hidden state
__device__ float g_c[BB * HDIM];                 // cell state

// ---------------------------------------------------------------------------
// init: zero h0 (buffer 0) and c0
// ---------------------------------------------------------------------------
__global__ void init_state_kernel() {
    int i = blockIdx.x * blockDim.x + threadIdx.x;
    g_h[0][i] = 0.f;
    g_c[i]    = 0.f;
}

// ---------------------------------------------------------------------------
// Wh re-layout: dest[k*4096 + j*4 + g] = Wh[k*4096 + g*1024 + j]
// Coalesced writes; scattered reads hit L2 (16 MB, one-time).
// ---------------------------------------------------------------------------
__global__ void transpose_wh_kernel(const float* __restrict__ Wh) {
    int idx = blockIdx.x * blockDim.x + threadIdx.x;
    int k   = idx >> 12;
    int rem = idx & 4095;
    int j   = rem >> 2;
    int g   = rem & 3;
    g_WhR[idx] = Wh[(k << 12) + (g << 10) + j];
}

// ---------------------------------------------------------------------------
// Phase 1: gates_x = x @ Wi + bi   (M=16384, K=512, N=4096)
// Classic 128x128x8 register-tiled SGEMM, 256 threads, 8x8 per thread.
// Writes into g_gates with [T][B][4H] layout (row m = b*256 + t).
// ---------------------------------------------------------------------------
__global__ void __launch_bounds__(256) gemm_x_kernel(
    const float* __restrict__ X,   // [16384, 512]
    const float* __restrict__ Wi,  // [512, 4096]
    const float* __restrict__ bi)  // [4096]
{
    __shared__ float As[8][128];   // [k][m] (transposed)
    __shared__ float Bs[8][128];   // [k][n]

    const int tid = threadIdx.x;
    const int m0  = blockIdx.y * 128;
    const int n0  = blockIdx.x * 128;
    const int tx  = tid & 15;   // n-thread
    const int ty  = tid >> 4;   // m-thread

    const int arow = tid >> 1;          // 0..127
    const int acol = (tid & 1) << 2;    // 0 or 4
    const int brow = tid >> 5;          // 0..7
    const int bcol = (tid & 31) << 2;   // 0..124

    float acc[8][8];
#pragma unroll
    for (int i = 0; i < 8; i++)
#pragma unroll
        for (int j = 0; j < 8; j++) acc[i][j] = 0.f;

    for (int k0 = 0; k0 < IDIM; k0 += 8) {
        float4 av = *(const float4*)(X + (size_t)(m0 + arow) * IDIM + k0 + acol);
        As[acol + 0][arow] = av.x;
        As[acol + 1][arow] = av.y;
        As[acol + 2][arow] = av.z;
        As[acol + 3][arow] = av.w;
        *(float4*)(&Bs[brow][bcol]) =
            *(const float4*)(Wi + (size_t)(k0 + brow) * G4 + n0 + bcol);
        __syncthreads();

#pragma unroll
        for (int k = 0; k < 8; k++) {
            float rm[8], rn[8];
            *(float4*)&rm[0] = *(float4*)&As[k][ty * 8];
            *(float4*)&rm[4] = *(float4*)&As[k][ty * 8 + 4];
            *(float4*)&rn[0] = *(float4*)&Bs[k][tx * 8];
            *(float4*)&rn[4] = *(float4*)&Bs[k][tx * 8 + 4];
#pragma unroll
            for (int i = 0; i < 8; i++)
#pragma unroll
                for (int j = 0; j < 8; j++)
                    acc[i][j] += rm[i] * rn[j];
        }
        __syncthreads();
    }

#pragma unroll
    for (int i = 0; i < 8; i++) {
        int m = m0 + ty * 8 + i;
        int b = m >> 8;     // / TT
        int t = m & 255;    // % TT
        float* dst = g_gates + (size_t)(t * BB + b) * G4 + n0 + tx * 8;
#pragma unroll
        for (int j = 0; j < 8; j++)
            dst[j] = acc[i][j] + bi[n0 + tx * 8 + j];
    }
}

// ---------------------------------------------------------------------------
// Phase 2: one timestep.
//   g[b, n] = gates_x[t,b,n] + (h @ Wh)[b,n] + bh[n];  LSTM pointwise.
// 128 blocks, each owns 8 hidden units j (all 4 gates), all 64 batch rows.
// K=1024 loop in BK=16 tiles with register prefetch (global latency hidden).
// Inner loop per k: 1 LDS.64 (h pair) + 1 LDS.128 (4 gate weights) + 8 FFMA.
// h double-buffered across steps (cross-block RAW hazard); c, Q block-private.
// ---------------------------------------------------------------------------
__global__ void __launch_bounds__(256) lstm_step_kernel(
    const float* __restrict__ bh,
    float* __restrict__ Q,   // d_out base: [B][T][HD]
    int t)
{
    __shared__ float Hs[16][66];   // [k][m], padded to kill STS conflicts
    __shared__ float Ws[16][32];   // [k][jj*4 + g]

    const int tid = threadIdx.x;
    const int j0  = blockIdx.x * 8;
    const int mi  = tid & 31;   // row-pair index (rows 2mi, 2mi+1)
    const int ji  = tid >> 5;   // 0..7 hidden unit within tile

    const float* __restrict__ hin  = g_h[t & 1];
    float* __restrict__ hout       = g_h[(t + 1) & 1];
    const float* __restrict__ gt   = g_gates + (size_t)t * BB * G4;

    // loader indices
    const int hm = tid >> 2;            // 0..63 (batch row)
    const int hc = (tid & 3) << 2;      // 0,4,8,12 (k within tile)
    const int wk = tid >> 4;            // 0..15
    const int wc = (tid & 15) << 1;     // 0..30

    float acc[2][4] = {{0.f,0.f,0.f,0.f},{0.f,0.f,0.f,0.f}};

    // prefetch tile 0
    float4 hreg = *(const float4*)(hin + hm * HDIM + hc);
    float2 wreg = *(const float2*)(g_WhR + (size_t)wk * G4 + j0 * 4 + wc);

    for (int k0 = 0; k0 < HDIM; k0 += 16) {
        Hs[hc + 0][hm] = hreg.x;
        Hs[hc + 1][hm] = hreg.y;
        Hs[hc + 2][hm] = hreg.z;
        Hs[hc + 3][hm] = hreg.w;
        Ws[wk][wc]     = wreg.x;
        Ws[wk][wc + 1] = wreg.y;
        __syncthreads();

        int kn = k0 + 16;
        if (kn < HDIM) {  // prefetch next tile (overlaps with compute below)
            hreg = *(const float4*)(hin + hm * HDIM + kn + hc);
            wreg = *(const float2*)(g_WhR + (size_t)(kn + wk) * G4 + j0 * 4 + wc);
        }

#pragma unroll
        for (int k = 0; k < 16; k++) {
            float2 hv = *(const float2*)&Hs[k][mi * 2];
            float4 wv = *(const float4*)&Ws[k][ji * 4];
            acc[0][0] += hv.x * wv.x;
            acc[0][1] += hv.x * wv.y;
            acc[0][2] += hv.x * wv.z;
            acc[0][3] += hv.x * wv.w;
            acc[1][0] += hv.y * wv.x;
            acc[1][1] += hv.y * wv.y;
            acc[1][2] += hv.y * wv.z;
            acc[1][3] += hv.y * wv.w;
        }
        __syncthreads();
    }

    const int j = j0 + ji;
#pragma unroll
    for (int r = 0; r < 2; r++) {
        int b = mi * 2 + r;
        float gf = acc[r][0] + gt[b * G4            + j] + bh[j];
        float gi = acc[r][1] + gt[b * G4 +   HDIM   + j] + bh[HDIM + j];
        float ga = acc[r][2] + gt[b * G4 + 2 * HDIM + j] + bh[2 * HDIM + j];
        float go = acc[r][3] + gt[b * G4 + 3 * HDIM + j] + bh[3 * HDIM + j];

        float f  = 1.f / (1.f + __expf(-gf));
        float ig = 1.f / (1.f + __expf(-gi));
        float a  = tanhf(ga);
        float o  = 1.f / (1.f + __expf(-go));

        float c = f * g_c[b * HDIM + j] + ig * a;
        float h = o * tanhf(c);

        g_c[b * HDIM + j]      = c;
        hout[b * HDIM + j]     = h;
        Q[(b * TT + t) * HDIM + j] = h;   // Q_all[b][t][j]
    }
}

// ---------------------------------------------------------------------------
// finalize: hT, cT appended after Q_all. T=256 even -> final h in buffer 0.
// ---------------------------------------------------------------------------
__global__ void finalize_kernel(float* __restrict__ out) {
    int i = blockIdx.x * blockDim.x + threadIdx.x;
    out[(size_t)BB * TT * HDIM + i]             = g_h[0][i];
    out[(size_t)BB * TT * HDIM + BB * HDIM + i] = g_c[i];
}

// ---------------------------------------------------------------------------
extern "C" void kernel_launch(void* const* d_in, const int* in_sizes, int n_in,
                              void* d_out, int out_size) {
    const float* x  = (const float*)d_in[0];   // [64,256,512]
    const float* Wi = (const float*)d_in[1];   // [512,4096]
    const float* bi = (const float*)d_in[2];   // [4096]
    const float* Wh = (const float*)d_in[3];   // [1024,4096]
    const float* bh = (const float*)d_in[4];   // [4096]
    float* out = (float*)d_out;

    init_state_kernel<<<(BB * HDIM) / 256, 256>>>();
    transpose_wh_kernel<<<(HDIM * G4) / 256, 256>>>(Wh);
    gemm_x_kernel<<<dim3(G4 / 128, (BB * TT) / 128), 256>>>(x, Wi, bi);
    for (int t = 0; t < TT; t++)
        lstm_step_kernel<<<HDIM / 8, 256>>>(bh, out, t);
    finalize_kernel<<<(BB * HDIM) / 256, 256>>>(out);
}

// round 2
// speedup vs baseline: 2.0670x; 2.0670x over previous
#include <cuda_runtime.h>
#include <math.h>
#include <stdint.h>

#define BB   64
#define TT   256
#define IDIM 512
#define HDIM 1024
#define G4   4096        // 4*HDIM
#define GRID 128         // persistent blocks (<=148, all resident)
#define CK   64          // h chunk size (K per staging tile)
#define HPAD 68          // padded row stride for Hs

// ---- device scratch ----
__device__ float    g_gates[(size_t)TT * BB * G4];  // [T][B][4H], bi+bh folded in
__device__ float    g_h[2][BB * HDIM];              // double-buffered hidden state
__device__ unsigned g_arrive;
__device__ unsigned g_gen;

// ---------------------------------------------------------------------------
__global__ void init_sync_kernel() {
    g_arrive = 0u;
    g_gen    = 0u;
}

// ---------------------------------------------------------------------------
// Phase 1: gates = x @ Wi + bi + bh   (M=16384, K=512, N=4096)
// 128x128x8 register-tiled SGEMM (fp32, exact).
// ---------------------------------------------------------------------------
__global__ void __launch_bounds__(256) gemm_x_kernel(
    const float* __restrict__ X,   // [16384, 512]
    const float* __restrict__ Wi,  // [512, 4096]
    const float* __restrict__ bi,  // [4096]
    const float* __restrict__ bh)  // [4096]
{
    __shared__ float As[8][128];   // [k][m]
    __shared__ float Bs[8][128];   // [k][n]

    const int tid = threadIdx.x;
    const int m0  = blockIdx.y * 128;
    const int n0  = blockIdx.x * 128;
    const int tx  = tid & 15;
    const int ty  = tid >> 4;

    const int arow = tid >> 1;
    const int acol = (tid & 1) << 2;
    const int brow = tid >> 5;
    const int bcol = (tid & 31) << 2;

    float acc[8][8];
#pragma unroll
    for (int i = 0; i < 8; i++)
#pragma unroll
        for (int j = 0; j < 8; j++) acc[i][j] = 0.f;

    for (int k0 = 0; k0 < IDIM; k0 += 8) {
        float4 av = *(const float4*)(X + (size_t)(m0 + arow) * IDIM + k0 + acol);
        As[acol + 0][arow] = av.x;
        As[acol + 1][arow] = av.y;
        As[acol + 2][arow] = av.z;
        As[acol + 3][arow] = av.w;
        *(float4*)(&Bs[brow][bcol]) =
            *(const float4*)(Wi + (size_t)(k0 + brow) * G4 + n0 + bcol);
        __syncthreads();

#pragma unroll
        for (int k = 0; k < 8; k++) {
            float rm[8], rn[8];
            *(float4*)&rm[0] = *(float4*)&As[k][ty * 8];
            *(float4*)&rm[4] = *(float4*)&As[k][ty * 8 + 4];
            *(float4*)&rn[0] = *(float4*)&Bs[k][tx * 8];
            *(float4*)&rn[4] = *(float4*)&Bs[k][tx * 8 + 4];
#pragma unroll
            for (int i = 0; i < 8; i++)
#pragma unroll
                for (int j = 0; j < 8; j++)
                    acc[i][j] += rm[i] * rn[j];
        }
        __syncthreads();
    }

#pragma unroll
    for (int i = 0; i < 8; i++) {
        int m = m0 + ty * 8 + i;
        int b = m >> 8;
        int t = m & 255;
        float* dst = g_gates + (size_t)(t * BB + b) * G4 + n0 + tx * 8;
#pragma unroll
        for (int j = 0; j < 8; j++) {
            int n = n0 + tx * 8 + j;
            dst[j] = acc[i][j] + bi[n] + bh[n];
        }
    }
}

// ---------------------------------------------------------------------------
// helpers
// ---------------------------------------------------------------------------
__device__ __forceinline__ float tf32r(float v) {
    uint32_t u;
    asm("cvt.rna.tf32.f32 %0, %1;" : "=r"(u) : "f"(v));
    return __uint_as_float(u);
}

__device__ __forceinline__ void mma_tf32(float d[4],
    uint32_t a0, uint32_t a1, uint32_t a2, uint32_t a3,
    uint32_t b0, uint32_t b1)
{
    asm volatile(
        "mma.sync.aligned.m16n8k8.row.col.f32.tf32.tf32.f32 "
        "{%0,%1,%2,%3},{%4,%5,%6,%7},{%8,%9},{%0,%1,%2,%3};\n"
        : "+f"(d[0]), "+f"(d[1]), "+f"(d[2]), "+f"(d[3])
        : "r"(a0), "r"(a1), "r"(a2), "r"(a3), "r"(b0), "r"(b1));
}

__device__ __forceinline__ float sigf(float x) {
    return 1.f / (1.f + __expf(-x));
}

// ---------------------------------------------------------------------------
// Phase 2: persistent LSTM recurrence. All 256 timesteps in one kernel.
//
// grid = 128 blocks (1/SM, all co-resident), 256 threads = 8 warps.
// Block bx owns hidden units j = bx*8 .. bx*8+7  (gate cols n = 4j+g).
// Per step: D[64 x 32] = h[64 x 1024] @ WhSlice[1024 x 32] via tf32 mma,
//           then LSTM pointwise with c held in registers.
//
// SMEM: Wf = Wh slice pre-swizzled into B-fragment order (128 KB, built once)
//       Hs = double-buffered h chunks [2][64][HPAD] (tf32-rounded)
// Sync: sense/gen atomic grid barrier, one per step (h double-buffered).
// ---------------------------------------------------------------------------
__global__ void __launch_bounds__(256, 1) lstm_persist_kernel(
    const float* __restrict__ Wh,   // [1024, 4096] original layout
    float* __restrict__ out)        // Q_all | hT | cT
{
    extern __shared__ float smem[];
    float2* Wf = (float2*)smem;                 // [128 ksteps][4 ct][32 lanes]
    float*  Hs = smem + 32768;                  // 2 * 64 * HPAD floats

    const int tid  = threadIdx.x;
    const int lane = tid & 31;
    const int wid  = tid >> 5;
    const int wm   = wid & 3;    // m16 group (rows wm*16..wm*16+15)
    const int wn   = wid >> 2;   // n16 group (cols wn*16..wn*16+15)
    const int bx   = blockIdx.x;

    // ---- build Wf: Wf[(s*4+ct)*32 + l] = (B[k][n], B[k+4][n]) tf32-rounded,
    //      k = 8s + (l&3), n = ct*8 + (l>>2),  B[k][n] = Wh[k][g*1024 + j],
    //      j = bx*8 + (n>>2), g = n&3
    for (int e = tid; e < 128 * 4 * 32; e += 256) {
        int l  = e & 31;
        int ct = (e >> 5) & 3;
        int s  = e >> 7;
        int k  = s * 8 + (l & 3);
        int n  = ct * 8 + (l >> 2);
        int j  = bx * 8 + (n >> 2);
        int g  = n & 3;
        float v0 = Wh[(size_t)k * G4 + g * 1024 + j];
        float v1 = Wh[(size_t)(k + 4) * G4 + g * 1024 + j];
        Wf[e] = make_float2(tf32r(v0), tf32r(v1));
    }
    __syncthreads();

    // ---- persistent per-lane state ----
    // epilogue mapping (per n8 subtile nt): lane -> one (b, j)
    const int kq   = lane & 3;
    const int rowg = lane >> 2;
    const int odd  = lane & 1;
    const int bmy  = wm * 16 + rowg + (odd ? 8 : 0);
    const int jbase = bx * 8 + wn * 4 + (kq >> 1);   // + nt*2

    float creg[2] = {0.f, 0.f};

    // A-fragment base offsets in Hs
    const int arow = wm * 16 + rowg;

    for (int t = 0; t < TT; t++) {
        float acc[2][4] = {{0.f,0.f,0.f,0.f},{0.f,0.f,0.f,0.f}};

        // prefetch this step's gates_x for the epilogue (hides DRAM latency)
        const float* __restrict__ gt = g_gates + (size_t)t * BB * G4;
        float gF[2], gI[2], gA[2], gO[2];
#pragma unroll
        for (int nt = 0; nt < 2; nt++) {
            int j = jbase + nt * 2;
            gF[nt] = __ldcg(gt + (size_t)bmy * G4 + j);
            gI[nt] = __ldcg(gt + (size_t)bmy * G4 + 1024 + j);
            gA[nt] = __ldcg(gt + (size_t)bmy * G4 + 2048 + j);
            gO[nt] = __ldcg(gt + (size_t)bmy * G4 + 3072 + j);
        }

        if (t > 0) {
            // ---- grid barrier: all blocks finished step t-1 ----
            __syncthreads();
            if (tid == 0) {
                __threadfence();
                unsigned a = atomicAdd(&g_arrive, 1u);
                if (a == GRID - 1u) {
                    g_arrive = 0u;
                    __threadfence();
                    atomicExch(&g_gen, (unsigned)t);
                } else {
                    while (atomicAdd(&g_gen, 0u) < (unsigned)t) { }
                }
            }
            __syncthreads();

            const float* __restrict__ hin = g_h[t & 1];

            // prefetch chunk 0 (16 floats/thread, coalesced, L2-only)
            float4 pf[4];
            {
                int fi = tid;
#pragma unroll
                for (int i = 0; i < 4; i++, fi += 256) {
                    int b   = fi >> 4;
                    int kk4 = fi & 15;
                    pf[i] = __ldcg((const float4*)(hin + (size_t)b * HDIM + kk4 * 4));
                }
            }

            int buf = 0;
            for (int ch = 0; ch < 16; ch++) {
                // store chunk (tf32-rounded)
                {
                    float* H = Hs + buf * (64 * HPAD);
                    int fi = tid;
#pragma unroll
                    for (int i = 0; i < 4; i++, fi += 256) {
                        int b   = fi >> 4;
                        int kk4 = fi & 15;
                        float4 v = pf[i];
                        v.x = tf32r(v.x); v.y = tf32r(v.y);
                        v.z = tf32r(v.z); v.w = tf32r(v.w);
                        *(float4*)(H + b * HPAD + kk4 * 4) = v;
                    }
                }
                __syncthreads();

                // prefetch next chunk
                if (ch < 15) {
                    int k0 = (ch + 1) * CK;
                    int fi = tid;
#pragma unroll
                    for (int i = 0; i < 4; i++, fi += 256) {
                        int b   = fi >> 4;
                        int kk4 = fi & 15;
                        pf[i] = __ldcg((const float4*)(hin + (size_t)b * HDIM + k0 + kk4 * 4));
                    }
                }

                // 8 k-steps of mma on this chunk
                const float* H = Hs + buf * (64 * HPAD) + arow * HPAD;
#pragma unroll
                for (int ks = 0; ks < 8; ks++) {
                    int col = ks * 8 + kq;
                    uint32_t a0 = __float_as_uint(H[col]);
                    uint32_t a1 = __float_as_uint(H[8 * HPAD + col]);
                    uint32_t a2 = __float_as_uint(H[col + 4]);
                    uint32_t a3 = __float_as_uint(H[8 * HPAD + col + 4]);
                    int s = ch * 8 + ks;
#pragma unroll
                    for (int nt = 0; nt < 2; nt++) {
                        float2 bv = Wf[(s * 4 + wn * 2 + nt) * 32 + lane];
                        mma_tf32(acc[nt], a0, a1, a2, a3,
                                 __float_as_uint(bv.x), __float_as_uint(bv.y));
                    }
                }
                buf ^= 1;
            }
            __syncthreads();
        }

        // ---- epilogue: shfl-pair gates, LSTM pointwise, write h/Q ----
        float* __restrict__ hout = g_h[(t + 1) & 1];
#pragma unroll
        for (int nt = 0; nt < 2; nt++) {
            float x0 = __shfl_xor_sync(0xffffffffu, acc[nt][0], 1);
            float x1 = __shfl_xor_sync(0xffffffffu, acc[nt][1], 1);
            float x2 = __shfl_xor_sync(0xffffffffu, acc[nt][2], 1);
            float x3 = __shfl_xor_sync(0xffffffffu, acc[nt][3], 1);

            float F, I, A, O;
            if (!odd) { F = acc[nt][0]; I = acc[nt][1]; A = x0; O = x1; }
            else      { F = x2;         I = x3;         A = acc[nt][2]; O = acc[nt][3]; }

            F += gF[nt]; I += gI[nt]; A += gA[nt]; O += gO[nt];

            float f = sigf(F);
            float i = sigf(I);
            float a = tanhf(A);
            float o = sigf(O);

            float c = f * creg[nt] + i * a;
            creg[nt] = c;
            float h = o * tanhf(c);

            int j = jbase + nt * 2;
            hout[(size_t)bmy * HDIM + j] = h;
            out[((size_t)bmy * TT + t) * HDIM + j] = h;
            if (t == TT - 1) {
                size_t qsz = (size_t)BB * TT * HDIM;
                out[qsz + (size_t)bmy * HDIM + j]             = h;
                out[qsz + BB * HDIM + (size_t)bmy * HDIM + j] = c;
            }
        }
    }
}

// ---------------------------------------------------------------------------
extern "C" void kernel_launch(void* const* d_in, const int* in_sizes, int n_in,
                              void* d_out, int out_size) {
    const float* x  = (const float*)d_in[0];
    const float* Wi = (const float*)d_in[1];
    const float* bi = (const float*)d_in[2];
    const float* Wh = (const float*)d_in[3];
    const float* bh = (const float*)d_in[4];
    float* out = (float*)d_out;

    const int smem_bytes = (32768 + 2 * 64 * HPAD) * 4;   // 165,888 B
    cudaFuncSetAttribute(lstm_persist_kernel,
                         cudaFuncAttributeMaxDynamicSharedMemorySize, smem_bytes);

    init_sync_kernel<<<1, 1>>>();
    gemm_x_kernel<<<dim3(G4 / 128, (BB * TT) / 128), 256>>>(x, Wi, bi, bh);
    lstm_persist_kernel<<<GRID, 256, smem_bytes>>>(Wh, out);
}

// round 3
// speedup vs baseline: 2.5414x; 1.2295x over previous
#include <cuda_runtime.h>
#include <math.h>
#include <stdint.h>

#define BB   64
#define TT   256
#define IDIM 512
#define HDIM 1024
#define G4   4096        // 4*HDIM
#define GRID 128         // persistent blocks (<=148, all resident)
#define CK   64          // h chunk size (K per staging tile)
#define HPAD 68          // padded row stride for Hs

// ---- device scratch ----
__device__ float    g_gates[(size_t)TT * BB * G4];  // [T][B][4H], bi+bh folded in
__device__ float    g_h[2][BB * HDIM];              // double-buffered hidden state
__device__ unsigned g_arrive;
__device__ unsigned g_gen;

// ---------------------------------------------------------------------------
__global__ void init_sync_kernel() {
    g_arrive = 0u;
    g_gen    = 0u;
}

// ---------------------------------------------------------------------------
// helpers
// ---------------------------------------------------------------------------
__device__ __forceinline__ float tf32r(float v) {
    uint32_t u;
    asm("cvt.rna.tf32.f32 %0, %1;" : "=r"(u) : "f"(v));
    return __uint_as_float(u);
}

__device__ __forceinline__ void mma_tf32(float d[4],
    uint32_t a0, uint32_t a1, uint32_t a2, uint32_t a3,
    uint32_t b0, uint32_t b1)
{
    asm volatile(
        "mma.sync.aligned.m16n8k8.row.col.f32.tf32.tf32.f32 "
        "{%0,%1,%2,%3},{%4,%5,%6,%7},{%8,%9},{%0,%1,%2,%3};\n"
        : "+f"(d[0]), "+f"(d[1]), "+f"(d[2]), "+f"(d[3])
        : "r"(a0), "r"(a1), "r"(a2), "r"(a3), "r"(b0), "r"(b1));
}

__device__ __forceinline__ float sigf(float x) {
    return 1.f / (1.f + __expf(-x));
}

// ---------------------------------------------------------------------------
// Phase 1: gates = x @ Wi + bi + bh   (M=16384, K=512, N=4096)  -- tf32 MMA
// 128x128 block tile, BK=16, 8 warps (2m x 4n), warp tile 64x32 (4x4 mma).
// ---------------------------------------------------------------------------
__global__ void __launch_bounds__(256) gemm_tc_kernel(
    const float* __restrict__ X,   // [16384, 512]
    const float* __restrict__ Wi,  // [512, 4096]
    const float* __restrict__ bi,  // [4096]
    const float* __restrict__ bh)  // [4096]
{
    __shared__ float As[16][132];   // [k][m] transposed, tf32-rounded
    __shared__ float Bs[16][132];   // [k][n]

    const int tid  = threadIdx.x;
    const int lane = tid & 31;
    const int w    = tid >> 5;
    const int wm   = w & 1;          // 0..1 (64 rows each)
    const int wn   = w >> 1;         // 0..3 (32 cols each)
    const int m0   = blockIdx.y * 128;
    const int n0   = blockIdx.x * 128;

    const int rowg = lane >> 2;      // 0..7
    const int kq   = lane & 3;       // 0..3

    // loader indices
    const int aRow = tid >> 1;           // 0..127
    const int aCol = (tid & 1) * 8;      // 0 or 8
    const int bRow = tid >> 5;           // 0..7 (also +8)
    const int bCol = (tid & 31) * 4;     // 0..124

    float acc[4][4][4];
#pragma unroll
    for (int mi = 0; mi < 4; mi++)
#pragma unroll
        for (int ni = 0; ni < 4; ni++)
#pragma unroll
            for (int q = 0; q < 4; q++) acc[mi][ni][q] = 0.f;

    for (int k0 = 0; k0 < IDIM; k0 += 16) {
        // load A tile: X[m0+aRow][k0+aCol .. +7] -> As[k][m] (transposed)
        float4 av0 = *(const float4*)(X + (size_t)(m0 + aRow) * IDIM + k0 + aCol);
        float4 av1 = *(const float4*)(X + (size_t)(m0 + aRow) * IDIM + k0 + aCol + 4);
        As[aCol + 0][aRow] = tf32r(av0.x);
        As[aCol + 1][aRow] = tf32r(av0.y);
        As[aCol + 2][aRow] = tf32r(av0.z);
        As[aCol + 3][aRow] = tf32r(av0.w);
        As[aCol + 4][aRow] = tf32r(av1.x);
        As[aCol + 5][aRow] = tf32r(av1.y);
        As[aCol + 6][aRow] = tf32r(av1.z);
        As[aCol + 7][aRow] = tf32r(av1.w);

        // load B tile: Wi[k0+bRow(+8)][n0+bCol..+3] -> Bs[k][n]
#pragma unroll
        for (int h = 0; h < 2; h++) {
            int kr = bRow + h * 8;
            float4 bv = *(const float4*)(Wi + (size_t)(k0 + kr) * G4 + n0 + bCol);
            bv.x = tf32r(bv.x); bv.y = tf32r(bv.y);
            bv.z = tf32r(bv.z); bv.w = tf32r(bv.w);
            *(float4*)(&Bs[kr][bCol]) = bv;
        }
        __syncthreads();

#pragma unroll
        for (int ks = 0; ks < 2; ks++) {
            const int kb = ks * 8;
            uint32_t af[4][4], bf[4][2];
#pragma unroll
            for (int mi = 0; mi < 4; mi++) {
                int r = wm * 64 + mi * 16 + rowg;
                af[mi][0] = __float_as_uint(As[kb + kq][r]);
                af[mi][1] = __float_as_uint(As[kb + kq][r + 8]);
                af[mi][2] = __float_as_uint(As[kb + kq + 4][r]);
                af[mi][3] = __float_as_uint(As[kb + kq + 4][r + 8]);
            }
#pragma unroll
            for (int ni = 0; ni < 4; ni++) {
                int c = wn * 32 + ni * 8 + rowg;
                bf[ni][0] = __float_as_uint(Bs[kb + kq][c]);
                bf[ni][1] = __float_as_uint(Bs[kb + kq + 4][c]);
            }
#pragma unroll
            for (int mi = 0; mi < 4; mi++)
#pragma unroll
                for (int ni = 0; ni < 4; ni++)
                    mma_tf32(acc[mi][ni], af[mi][0], af[mi][1], af[mi][2], af[mi][3],
                             bf[ni][0], bf[ni][1]);
        }
        __syncthreads();
    }

    // epilogue: D frag (rowg, 2kq),(rowg,2kq+1) / (rowg+8, ...) -> g_gates[t][b][n]
#pragma unroll
    for (int ni = 0; ni < 4; ni++) {
        int n = n0 + wn * 32 + ni * 8 + 2 * kq;
        float bias0 = bi[n] + bh[n];
        float bias1 = bi[n + 1] + bh[n + 1];
#pragma unroll
        for (int mi = 0; mi < 4; mi++) {
            int m  = m0 + wm * 64 + mi * 16 + rowg;
            {
                int b = m >> 8, t = m & 255;
                float2 v = make_float2(acc[mi][ni][0] + bias0, acc[mi][ni][1] + bias1);
                *(float2*)(g_gates + (size_t)(t * BB + b) * G4 + n) = v;
            }
            {
                int m2 = m + 8;
                int b = m2 >> 8, t = m2 & 255;
                float2 v = make_float2(acc[mi][ni][2] + bias0, acc[mi][ni][3] + bias1);
                *(float2*)(g_gates + (size_t)(t * BB + b) * G4 + n) = v;
            }
        }
    }
}

// ---------------------------------------------------------------------------
// Phase 2: persistent LSTM recurrence. All 256 timesteps in one kernel.
// (unchanged from R2 — known good)
// ---------------------------------------------------------------------------
__global__ void __launch_bounds__(256, 1) lstm_persist_kernel(
    const float* __restrict__ Wh,   // [1024, 4096] original layout
    float* __restrict__ out)        // Q_all | hT | cT
{
    extern __shared__ float smem[];
    float2* Wf = (float2*)smem;                 // [128 ksteps][4 ct][32 lanes]
    float*  Hs = smem + 32768;                  // 2 * 64 * HPAD floats

    const int tid  = threadIdx.x;
    const int lane = tid & 31;
    const int wid  = tid >> 5;
    const int wm   = wid & 3;    // m16 group
    const int wn   = wid >> 2;   // n16 group
    const int bx   = blockIdx.x;

    // build Wf (B-fragment order, tf32-rounded), once
    for (int e = tid; e < 128 * 4 * 32; e += 256) {
        int l  = e & 31;
        int ct = (e >> 5) & 3;
        int s  = e >> 7;
        int k  = s * 8 + (l & 3);
        int n  = ct * 8 + (l >> 2);
        int j  = bx * 8 + (n >> 2);
        int g  = n & 3;
        float v0 = Wh[(size_t)k * G4 + g * 1024 + j];
        float v1 = Wh[(size_t)(k + 4) * G4 + g * 1024 + j];
        Wf[e] = make_float2(tf32r(v0), tf32r(v1));
    }
    __syncthreads();

    const int kq   = lane & 3;
    const int rowg = lane >> 2;
    const int odd  = lane & 1;
    const int bmy  = wm * 16 + rowg + (odd ? 8 : 0);
    const int jbase = bx * 8 + wn * 4 + (kq >> 1);

    float creg[2] = {0.f, 0.f};
    const int arow = wm * 16 + rowg;

    for (int t = 0; t < TT; t++) {
        float acc[2][4] = {{0.f,0.f,0.f,0.f},{0.f,0.f,0.f,0.f}};

        const float* __restrict__ gt = g_gates + (size_t)t * BB * G4;
        float gF[2], gI[2], gA[2], gO[2];
#pragma unroll
        for (int nt = 0; nt < 2; nt++) {
            int j = jbase + nt * 2;
            gF[nt] = __ldcg(gt + (size_t)bmy * G4 + j);
            gI[nt] = __ldcg(gt + (size_t)bmy * G4 + 1024 + j);
            gA[nt] = __ldcg(gt + (size_t)bmy * G4 + 2048 + j);
            gO[nt] = __ldcg(gt + (size_t)bmy * G4 + 3072 + j);
        }

        if (t > 0) {
            __syncthreads();
            if (tid == 0) {
                __threadfence();
                unsigned a = atomicAdd(&g_arrive, 1u);
                if (a == GRID - 1u) {
                    g_arrive = 0u;
                    __threadfence();
                    atomicExch(&g_gen, (unsigned)t);
                } else {
                    while (atomicAdd(&g_gen, 0u) < (unsigned)t) { }
                }
            }
            __syncthreads();

            const float* __restrict__ hin = g_h[t & 1];

            float4 pf[4];
            {
                int fi = tid;
#pragma unroll
                for (int i = 0; i < 4; i++, fi += 256) {
                    int b   = fi >> 4;
                    int kk4 = fi & 15;
                    pf[i] = __ldcg((const float4*)(hin + (size_t)b * HDIM + kk4 * 4));
                }
            }

            int buf = 0;
            for (int ch = 0; ch < 16; ch++) {
                {
                    float* H = Hs + buf * (64 * HPAD);
                    int fi = tid;
#pragma unroll
                    for (int i = 0; i < 4; i++, fi += 256) {
                        int b   = fi >> 4;
                        int kk4 = fi & 15;
                        float4 v = pf[i];
                        v.x = tf32r(v.x); v.y = tf32r(v.y);
                        v.z = tf32r(v.z); v.w = tf32r(v.w);
                        *(float4*)(H + b * HPAD + kk4 * 4) = v;
                    }
                }
                __syncthreads();

                if (ch < 15) {
                    int k0 = (ch + 1) * CK;
                    int fi = tid;
#pragma unroll
                    for (int i = 0; i < 4; i++, fi += 256) {
                        int b   = fi >> 4;
                        int kk4 = fi & 15;
                        pf[i] = __ldcg((const float4*)(hin + (size_t)b * HDIM + k0 + kk4 * 4));
                    }
                }

                const float* H = Hs + buf * (64 * HPAD) + arow * HPAD;
#pragma unroll
                for (int ks = 0; ks < 8; ks++) {
                    int col = ks * 8 + kq;
                    uint32_t a0 = __float_as_uint(H[col]);
                    uint32_t a1 = __float_as_uint(H[8 * HPAD + col]);
                    uint32_t a2 = __float_as_uint(H[col + 4]);
                    uint32_t a3 = __float_as_uint(H[8 * HPAD + col + 4]);
                    int s = ch * 8 + ks;
#pragma unroll
                    for (int nt = 0; nt < 2; nt++) {
                        float2 bv = Wf[(s * 4 + wn * 2 + nt) * 32 + lane];
                        mma_tf32(acc[nt], a0, a1, a2, a3,
                                 __float_as_uint(bv.x), __float_as_uint(bv.y));
                    }
                }
                buf ^= 1;
            }
            __syncthreads();
        }

        float* __restrict__ hout = g_h[(t + 1) & 1];
#pragma unroll
        for (int nt = 0; nt < 2; nt++) {
            float x0 = __shfl_xor_sync(0xffffffffu, acc[nt][0], 1);
            float x1 = __shfl_xor_sync(0xffffffffu, acc[nt][1], 1);
            float x2 = __shfl_xor_sync(0xffffffffu, acc[nt][2], 1);
            float x3 = __shfl_xor_sync(0xffffffffu, acc[nt][3], 1);

            float F, I, A, O;
            if (!odd) { F = acc[nt][0]; I = acc[nt][1]; A = x0; O = x1; }
            else      { F = x2;         I = x3;         A = acc[nt][2]; O = acc[nt][3]; }

            F += gF[nt]; I += gI[nt]; A += gA[nt]; O += gO[nt];

            float f = sigf(F);
            float i = sigf(I);
            float a = tanhf(A);
            float o = sigf(O);

            float c = f * creg[nt] + i * a;
            creg[nt] = c;
            float h = o * tanhf(c);

            int j = jbase + nt * 2;
            hout[(size_t)bmy * HDIM + j] = h;
            out[((size_t)bmy * TT + t) * HDIM + j] = h;
            if (t == TT - 1) {
                size_t qsz = (size_t)BB * TT * HDIM;
                out[qsz + (size_t)bmy * HDIM + j]             = h;
                out[qsz + BB * HDIM + (size_t)bmy * HDIM + j] = c;
            }
        }
    }
}

// ---------------------------------------------------------------------------
extern "C" void kernel_launch(void* const* d_in, const int* in_sizes, int n_in,
                              void* d_out, int out_size) {
    const float* x  = (const float*)d_in[0];
    const float* Wi = (const float*)d_in[1];
    const float* bi = (const float*)d_in[2];
    const float* Wh = (const float*)d_in[3];
    const float* bh = (const float*)d_in[4];
    float* out = (float*)d_out;

    const int smem_bytes = (32768 + 2 * 64 * HPAD) * 4;   // 165,888 B
    cudaFuncSetAttribute(lstm_persist_kernel,
                         cudaFuncAttributeMaxDynamicSharedMemorySize, smem_bytes);

    init_sync_kernel<<<1, 1>>>();
    gemm_tc_kernel<<<dim3(G4 / 128, (BB * TT) / 128), 256>>>(x, Wi, bi, bh);
    lstm_persist_kernel<<<GRID, 256, smem_bytes>>>(Wh, out);
}